// round 2
// baseline (speedup 1.0000x reference)
#include <cuda_runtime.h>
#include <cstdint>

#define W 131072
#define J 21
#define NB 20

// weights folded with denominators
#define C_PROJ   (1.0f / 42.0f)    // W_PROJ / (2*J)
#define C_BONE   (1.0f / 20.0f)    // W_BONE / (J-1)
#define C_SMOOTH (0.5f / 63.0f)    // W_SMOOTH / (3*J)
#define C_LIFT   (0.1f / 63.0f)    // W_LIFT / (3*J)

__device__ double g_acc;

__global__ void zero_acc_kernel() { g_acc = 0.0; }

__global__ void finalize_kernel(float* out) { out[0] = (float)g_acc; }

__global__ __launch_bounds__(256)
void loss_kernel(const float* __restrict__ pose,   // [(W+1),3,J]
                 const float* __restrict__ cam,    // [W,2,3]
                 const float* __restrict__ p2d,    // [W,2,J]
                 const float* __restrict__ blen,   // [NB]
                 const float* __restrict__ lift,   // [W,3,NB]
                 const int*   __restrict__ bc,     // [NB,2]
                 const int*   __restrict__ lbc)    // [NB,2]
{
    const int n = blockIdx.x * blockDim.x + threadIdx.x;
    float acc = 0.0f;

    if (n < W * J) {
        const int w = n / J;
        const int j = n - w * J;

        const float* pf1 = pose + (size_t)(w + 1) * 63;   // frame w+1
        const float x = pf1[j];
        const float y = pf1[21 + j];
        const float z = pf1[42 + j];

        // ---- projection loss ----
        const float* c = cam + (size_t)w * 6;
        const float* q = p2d + (size_t)w * 42;
        float px = c[0] * x + c[1] * y + c[2] * z - q[j];
        float py = c[3] * x + c[4] * y + c[5] * z - q[21 + j];
        acc += C_PROJ * (px * px + py * py);

        // ---- smoothness loss (second difference, t = w, valid for w >= 1) ----
        if (w >= 1) {
            const float* pf0 = pose + (size_t)w * 63;
            const float* pfm = pose + (size_t)(w - 1) * 63;
            float s = 0.0f;
            #pragma unroll
            for (int k = 0; k < 3; k++) {
                const int e = k * 21 + j;
                float a = pf1[e] - 2.0f * pf0[e] + pfm[e];
                s += a * a;
            }
            acc += C_SMOOTH * s;
        }

        // ---- per-bone terms (bone b = j for j < 20) ----
        if (j < NB) {
            const int b = j;

            // bone length loss, frame w+1
            const int ch = bc[2 * b];
            const int pa = bc[2 * b + 1];
            {
                float dx = pf1[ch]      - pf1[pa];
                float dy = pf1[21 + ch] - pf1[21 + pa];
                float dz = pf1[42 + ch] - pf1[42 + pa];
                float len = dx * dx + dy * dy + dz * dz;
                float e = len - blen[b];
                acc += C_BONE * e * e;
            }
            // bone length loss, frame 0 (done once, by the w==0 threads)
            if (w == 0) {
                const float* p0 = pose;
                float dx = p0[ch]      - p0[pa];
                float dy = p0[21 + ch] - p0[21 + pa];
                float dz = p0[42 + ch] - p0[42 + pa];
                float len = dx * dx + dy * dy + dz * dz;
                float e = len - blen[b];
                acc += C_BONE * e * e;
            }

            // lift direction loss (frames 1..W -> pf1)
            const int lch = lbc[2 * b];
            const int lpa = lbc[2 * b + 1];
            float bx = pf1[lch]      - pf1[lpa];
            float by = pf1[21 + lch] - pf1[21 + lpa];
            float bz = pf1[42 + lch] - pf1[42 + lpa];
            float inv = 1.0f / sqrtf(bx * bx + by * by + bz * bz);
            const float* ld = lift + (size_t)w * 60;
            float ex = ld[b]      - bx * inv;
            float ey = ld[20 + b] - by * inv;
            float ez = ld[40 + b] - bz * inv;
            acc += C_LIFT * (ex * ex + ey * ey + ez * ez);
        }
    }

    // ---- reduction: warp shuffle -> smem -> block sum -> double atomic ----
    #pragma unroll
    for (int off = 16; off > 0; off >>= 1)
        acc += __shfl_down_sync(0xFFFFFFFFu, acc, off);

    __shared__ float warp_sums[8];
    const int lane = threadIdx.x & 31;
    const int wid  = threadIdx.x >> 5;
    if (lane == 0) warp_sums[wid] = acc;
    __syncthreads();

    if (wid == 0) {
        float v = (lane < 8) ? warp_sums[lane] : 0.0f;
        #pragma unroll
        for (int off = 4; off > 0; off >>= 1)
            v += __shfl_down_sync(0xFFFFFFFFu, v, off);
        if (lane == 0)
            atomicAdd(&g_acc, (double)v);
    }
}

extern "C" void kernel_launch(void* const* d_in, const int* in_sizes, int n_in,
                              void* d_out, int out_size)
{
    const float* pose = (const float*)d_in[0];
    const float* cam  = (const float*)d_in[1];
    const float* p2d  = (const float*)d_in[2];
    const float* blen = (const float*)d_in[3];
    const float* lift = (const float*)d_in[4];
    const int*   bc   = (const int*)d_in[5];
    const int*   lbc  = (const int*)d_in[6];
    float* out = (float*)d_out;

    zero_acc_kernel<<<1, 1>>>();

    const int total = W * J;
    const int block = 256;
    const int grid = (total + block - 1) / block;
    loss_kernel<<<grid, block>>>(pose, cam, p2d, blen, lift, bc, lbc);

    finalize_kernel<<<1, 1>>>(out);
}